// round 17
// baseline (speedup 1.0000x reference)
#include <cuda_runtime.h>
#include <cuda_fp16.h>
#include <math.h>
#include <stdint.h>

#define N_TOK 8192
#define EMB   1024
#define DFF   4096
#define TSEQ  2048

// ---------------- scratch (device globals; no allocations allowed) ----------
__device__ float g_x1 [N_TOK * EMB];
__device__ float g_rowsum[N_TOK];
__device__ float g_rowsq [N_TOK];
__device__ float g_var[2];

__device__ __half g_h  [N_TOK * EMB];
__device__ __half g_qh [N_TOK * EMB];
__device__ __half g_kh [N_TOK * EMB];
__device__ __half g_vh [N_TOK * EMB];
__device__ __half g_ctx[N_TOK * EMB];
__device__ __half g_ff [N_TOK * DFF];
__device__ __half g_wq[EMB * EMB], g_wk[EMB * EMB], g_wv[EMB * EMB], g_wo[EMB * EMB];
__device__ __half g_l1[DFF * EMB], g_l2[EMB * DFF];

union HF2 { __half h[2]; uint32_t u; };
union HF4 { __half h[4]; uint2 u; };

__device__ __forceinline__ uint32_t smem_u32(const void* p) {
    uint32_t a;
    asm("{ .reg .u64 t; cvta.to.shared.u64 t, %1; cvt.u32.u64 %0, t; }" : "=r"(a) : "l"(p));
    return a;
}
__device__ __forceinline__ void cp16(uint32_t dst, const void* src) {
    asm volatile("cp.async.cg.shared.global [%0], [%1], 16;" :: "r"(dst), "l"(src) : "memory");
}
__device__ __forceinline__ void cp_commit() {
    asm volatile("cp.async.commit_group;" ::: "memory");
}
template <int N>
__device__ __forceinline__ void cp_wait() {
    asm volatile("cp.async.wait_group %0;" :: "n"(N) : "memory");
}
__device__ __forceinline__ void ldmx4(uint32_t* r, uint32_t addr) {
    asm volatile("ldmatrix.sync.aligned.m8n8.x4.shared.b16 {%0,%1,%2,%3}, [%4];"
                 : "=r"(r[0]), "=r"(r[1]), "=r"(r[2]), "=r"(r[3]) : "r"(addr));
}
__device__ __forceinline__ void ldmx4t(uint32_t* r, uint32_t addr) {
    asm volatile("ldmatrix.sync.aligned.m8n8.x4.trans.shared.b16 {%0,%1,%2,%3}, [%4];"
                 : "=r"(r[0]), "=r"(r[1]), "=r"(r[2]), "=r"(r[3]) : "r"(addr));
}
__device__ __forceinline__ void mma_f16(float* c, const uint32_t* a, const uint32_t* b) {
    asm volatile("mma.sync.aligned.m16n8k16.row.col.f32.f16.f16.f32 "
                 "{%0,%1,%2,%3}, {%4,%5,%6,%7}, {%8,%9}, {%0,%1,%2,%3};"
                 : "+f"(c[0]), "+f"(c[1]), "+f"(c[2]), "+f"(c[3])
                 : "r"(a[0]), "r"(a[1]), "r"(a[2]), "r"(a[3]), "r"(b[0]), "r"(b[1]));
}
__device__ __forceinline__ uint32_t sw128(uint32_t o) { return o ^ ((o >> 3) & 0x70); }

// ---------------- fused weight split (all 6 matrices, hi only) ---------------
#define SQ4 (EMB * EMB / 4)
#define SL4 (DFF * EMB / 4)
#define SPLIT_TOTAL4 (4 * SQ4 + 2 * SL4)

__global__ void split_all_kernel(const float* __restrict__ wq, const float* __restrict__ wk,
                                 const float* __restrict__ wv, const float* __restrict__ wo,
                                 const float* __restrict__ l1, const float* __restrict__ l2,
                                 __half* __restrict__ dq, __half* __restrict__ dk,
                                 __half* __restrict__ dv, __half* __restrict__ doo,
                                 __half* __restrict__ d1, __half* __restrict__ d2) {
    int i = blockIdx.x * blockDim.x + threadIdx.x;
    const float* src;
    __half* dst;
    int j;
    if (i < 4 * SQ4) {
        int m = i >> 18;
        j = i & (SQ4 - 1);
        src = (m == 0) ? wq : (m == 1) ? wk : (m == 2) ? wv : wo;
        dst = (m == 0) ? dq : (m == 1) ? dk : (m == 2) ? dv : doo;
    } else {
        int t = i - 4 * SQ4;
        if (t < SL4) { src = l1; dst = d1; j = t; }
        else         { src = l2; dst = d2; j = t - SL4; }
    }
    float4 v = ((const float4*)src)[j];
    HF4 H;
#pragma unroll
    for (int c = 0; c < 4; c++) H.h[c] = __float2half_rn((&v.x)[c]);
    ((uint2*)dst)[j] = H.u;
}

// ---------------- LN pieces ---------------------------------------------------
__global__ void rowstats_kernel(const float* __restrict__ x,
                                float* __restrict__ rowsum,
                                float* __restrict__ rowsq) {
    int row = blockIdx.x, tid = threadIdx.x;
    float4 v = *(const float4*)(x + (size_t)row * EMB + tid * 4);
    float s = v.x + v.y + v.z + v.w;
    float q = v.x * v.x + v.y * v.y + v.z * v.z + v.w * v.w;
#pragma unroll
    for (int o = 16; o > 0; o >>= 1) {
        s += __shfl_down_sync(0xffffffffu, s, o);
        q += __shfl_down_sync(0xffffffffu, q, o);
    }
    __shared__ float ss[8], qs[8];
    int w = tid >> 5, lane = tid & 31;
    if (lane == 0) { ss[w] = s; qs[w] = q; }
    __syncthreads();
    if (tid == 0) {
        float S = 0.f, Q = 0.f;
#pragma unroll
        for (int i = 0; i < 8; i++) { S += ss[i]; Q += qs[i]; }
        rowsum[row] = S; rowsq[row] = Q;
    }
}

__global__ void finalize_var_kernel(const float* __restrict__ rowsum,
                                    const float* __restrict__ rowsq,
                                    float* __restrict__ varout) {
    int tid = threadIdx.x;
    double s = 0.0, q = 0.0;
    for (int i = tid; i < N_TOK; i += 256) { s += (double)rowsum[i]; q += (double)rowsq[i]; }
#pragma unroll
    for (int o = 16; o > 0; o >>= 1) {
        s += __shfl_down_sync(0xffffffffu, s, o);
        q += __shfl_down_sync(0xffffffffu, q, o);
    }
    __shared__ double sd[8], qd[8];
    int w = tid >> 5, lane = tid & 31;
    if (lane == 0) { sd[w] = s; qd[w] = q; }
    __syncthreads();
    if (tid == 0) {
        double S = 0.0, Q = 0.0;
        for (int i = 0; i < 8; i++) { S += sd[i]; Q += qd[i]; }
        double M = (double)N_TOK * (double)EMB;
        double mean = S / M;
        varout[0] = (float)(Q / M - mean * mean);
    }
}

__global__ void ln_apply_hi_kernel(const float* __restrict__ x,
                                   const float* __restrict__ rowsum,
                                   const float* __restrict__ varp,
                                   const float* __restrict__ scale,
                                   const float* __restrict__ shift,
                                   __half* __restrict__ hi) {
    size_t i4 = (size_t)blockIdx.x * blockDim.x + threadIdx.x;
    size_t off = i4 * 4;
    int row = (int)(off >> 10), col = (int)(off & 1023);
    float invv = 1.0f / varp[0];
    float mean = rowsum[row] * (1.0f / 1024.0f);
    float4 v  = *(const float4*)(x + off);
    float4 sc = *(const float4*)(scale + col);
    float4 sh = *(const float4*)(shift + col);
    float o[4];
    o[0] = ((v.x - mean) * invv + 1e-5f) * sc.x + sh.x;
    o[1] = ((v.y - mean) * invv + 1e-5f) * sc.y + sh.y;
    o[2] = ((v.z - mean) * invv + 1e-5f) * sc.z + sh.z;
    o[3] = ((v.w - mean) * invv + 1e-5f) * sc.w + sh.w;
    HF4 H;
#pragma unroll
    for (int j = 0; j < 4; j++) H.h[j] = __float2half_rn(o[j]);
    ((uint2*)hi)[i4] = H.u;
}

// ---------------- fp16 1-pass GEMM, BK=64, 3-stage pipeline ------------------
enum { MODE_BIAS_RES = 1, MODE_GELU_HI = 2, MODE_BIAS_HI = 3 };

#define STAGE_BYTES 32768
#define MM_SMEM (3 * STAGE_BYTES)

template <int MODE>
__device__ __forceinline__ void gemm_body(
    const __half* __restrict__ Ah, const __half* __restrict__ Bh,
    const float* __restrict__ bias, const float* __restrict__ res,
    float* __restrict__ C, __half* __restrict__ Oh,
    int N, int K, float oscale, int bxx, int byy, char* smg) {
    const uint32_t sb = smem_u32(smg);
    const int tid = threadIdx.x, wid = tid >> 5, lane = tid & 31;
    const int warpM = wid >> 2;
    const int warpN = wid & 3;
    const size_t rowA0 = (size_t)byy * 128;
    const size_t rowB0 = (size_t)bxx * 128;

    const int gi = tid & 7;
    const int r0 = tid >> 3;
    uint32_t so[4];
#pragma unroll
    for (int i = 0; i < 4; i++)
        so[i] = sw128((uint32_t)((r0 + 32 * i) * 128 + gi * 16));

    const int NC = K / 64;
    auto cpchunk = [&](int c, int st) {
        if (c < NC) {
            uint32_t base = sb + st * STAGE_BYTES;
            int k0 = c * 64;
#pragma unroll
            for (int i = 0; i < 4; i++) {
                int r = r0 + 32 * i;
                size_t oa = (rowA0 + r) * (size_t)K + k0 + gi * 8;
                size_t ob = (rowB0 + r) * (size_t)K + k0 + gi * 8;
                cp16(base + so[i], Ah + oa);
                cp16(base + 16384 + so[i], Bh + ob);
            }
        }
        cp_commit();   // empty group when out of range keeps in-flight count uniform
    };

    float acc[4][4][4];
#pragma unroll
    for (int mi = 0; mi < 4; mi++)
#pragma unroll
        for (int ni = 0; ni < 4; ni++)
#pragma unroll
            for (int j = 0; j < 4; j++) acc[mi][ni][j] = 0.0f;

    cpchunk(0, 0);
    cpchunk(1, 1);
    for (int c = 0; c < NC; ++c) {
        cp_wait<1>();          // chunk c complete (2 newer groups may be in flight)
        __syncthreads();       // all warps done with stage (c-1)%3 and see stage c%3
        cpchunk(c + 2, (c + 2) % 3);

        uint32_t base = sb + (c % 3) * STAGE_BYTES;
#pragma unroll
        for (int ks = 0; ks < 4; ks++) {
            uint32_t bh[4][2];
#pragma unroll
            for (int np = 0; np < 2; np++) {
                int row = warpN * 32 + np * 16 + (lane & 15);
                uint32_t sw = sw128((uint32_t)(row * 128 + ks * 32 + (lane & 16)));
                uint32_t t[4];
                ldmx4(t, base + 16384 + sw);
                bh[np * 2][0] = t[0]; bh[np * 2][1] = t[2];
                bh[np * 2 + 1][0] = t[1]; bh[np * 2 + 1][1] = t[3];
            }
#pragma unroll
            for (int mi = 0; mi < 4; mi++) {
                int row = warpM * 64 + mi * 16 + (lane & 15);
                uint32_t sw = sw128((uint32_t)(row * 128 + ks * 32 + (lane & 16)));
                uint32_t ah[4];
                ldmx4(ah, base + sw);
#pragma unroll
                for (int ni = 0; ni < 4; ni++)
                    mma_f16(acc[mi][ni], ah, bh[ni]);
            }
        }
    }

    const int rbase = (int)rowA0 + warpM * 64 + (lane >> 2);
    const int cbase = (int)rowB0 + warpN * 32 + (lane & 3) * 2;
#pragma unroll
    for (int mi = 0; mi < 4; mi++) {
#pragma unroll
        for (int ni = 0; ni < 4; ni++) {
            int cg = cbase + ni * 8;
            float2 bv = *(const float2*)(bias + cg);
#pragma unroll
            for (int h = 0; h < 2; h++) {
                int rg = rbase + mi * 16 + h * 8;
                float o0 = acc[mi][ni][2 * h]     + bv.x;
                float o1 = acc[mi][ni][2 * h + 1] + bv.y;
                size_t off = (size_t)rg * N + cg;
                if (MODE == MODE_BIAS_RES) {
                    float2 r = *(const float2*)(res + off);
                    o0 += r.x; o1 += r.y;
                    float2 w; w.x = o0; w.y = o1;
                    *(float2*)(C + off) = w;
                } else if (MODE == MODE_GELU_HI) {
                    float g0 = 0.5f * o0 * (1.0f + erff(o0 * 0.70710678118654752f));
                    float g1 = 0.5f * o1 * (1.0f + erff(o1 * 0.70710678118654752f));
                    HF2 H;
                    H.h[0] = __float2half_rn(g0);
                    H.h[1] = __float2half_rn(g1);
                    *(uint32_t*)(Oh + off) = H.u;
                } else {  // MODE_BIAS_HI
                    HF2 H;
                    H.h[0] = __float2half_rn(o0 * oscale);
                    H.h[1] = __float2half_rn(o1 * oscale);
                    *(uint32_t*)(Oh + off) = H.u;
                }
            }
        }
    }
}

template <int MODE>
__global__ __launch_bounds__(256, 2)
void mmagemm_kernel(const __half* __restrict__ Ah, const __half* __restrict__ Bh,
                    const float* __restrict__ bias, const float* __restrict__ res,
                    float* __restrict__ C, __half* __restrict__ Oh,
                    int N, int K, float oscale) {
    extern __shared__ char smg[];
    gemm_body<MODE>(Ah, Bh, bias, res, C, Oh, N, K, oscale,
                    blockIdx.x, blockIdx.y, smg);
}

// fused QKV (1-pass): blockIdx.x in [0,24): sel = x>>3, col block = x&7
__global__ __launch_bounds__(256, 2)
void qkv_kernel(const __half* __restrict__ Ah,
                const __half* __restrict__ Bq, const __half* __restrict__ Bk,
                const __half* __restrict__ Bv,
                const float* __restrict__ b0, const float* __restrict__ b1,
                const float* __restrict__ b2,
                __half* __restrict__ Qh, __half* __restrict__ Kh,
                __half* __restrict__ Vh) {
    extern __shared__ char smg[];
    const int sel = blockIdx.x >> 3;
    const int bxx = blockIdx.x & 7;
    const __half* Bh = (sel == 0) ? Bq : (sel == 1) ? Bk : Bv;
    const float* bias = (sel == 0) ? b0 : (sel == 1) ? b1 : b2;
    __half* Oh = (sel == 0) ? Qh : (sel == 1) ? Kh : Vh;
    const float sc = (sel == 0) ? 0.125f : 1.0f;
    gemm_body<MODE_BIAS_HI>(Ah, Bh, bias, nullptr, nullptr, Oh,
                            EMB, EMB, sc, bxx, blockIdx.y, smg);
}

// ---------------- fp16 TC causal flash attention, 3-stage KV pipeline --------
// smem: Q 0 (16K); KV stages at 16384 + st*16384 (Kh +0, Vh +8192). Total 64K.
#define ATT_SMEM 65536

__global__ __launch_bounds__(256)
void attn_tc_kernel(const __half* __restrict__ Qh_, const __half* __restrict__ Kh_,
                    const __half* __restrict__ Vh_, __half* __restrict__ Oh) {
    extern __shared__ char smg[];
    const uint32_t sb = smem_u32(smg);
    const int qt   = (TSEQ / 128 - 1) - blockIdx.x;
    const int bh   = blockIdx.y;
    const int bb   = bh >> 4;
    const int head = bh & 15;
    const int tid  = threadIdx.x;
    const int wid  = tid >> 5;
    const int lane = tid & 31;
    const size_t hoff = (size_t)head * 64;
    const size_t seq0 = (size_t)bb * TSEQ;

    const int gi  = tid & 7;
    const int r32 = tid >> 3;
    const int ktlast = 2 * qt + 1;

    {
#pragma unroll
        for (int i = 0; i < 4; i++) {
            int r = r32 + 32 * i;
            size_t g = (seq0 + qt * 128 + r) * EMB + hoff + gi * 8;
            uint32_t sw = sw128((uint32_t)(r * 128 + gi * 16));
            cp16(sb + sw, Qh_ + g);
        }
        cp_commit();
    }
    auto cpKV = [&](int kt, int st) {
        if (kt <= ktlast) {
            uint32_t base = sb + 16384 + st * 16384;
#pragma unroll
            for (int i = 0; i < 2; i++) {
                int r = r32 + 32 * i;
                size_t g = (seq0 + kt * 64 + r) * EMB + hoff + gi * 8;
                uint32_t sw = sw128((uint32_t)(r * 128 + gi * 16));
                cp16(base + sw, Kh_ + g);
                cp16(base + 8192 + sw, Vh_ + g);
            }
        }
        cp_commit();
    };
    cpKV(0, 0);
    cpKV(1, 1);
    cp_wait<2>();   // Q group done (2 KV groups may be pending)
    __syncthreads();

    uint32_t qh[4][4];
#pragma unroll
    for (int ks = 0; ks < 4; ks++) {
        int row = wid * 16 + (lane & 15);
        uint32_t sw = sw128((uint32_t)(row * 128 + ks * 32 + (lane & 16)));
        ldmx4(qh[ks], sb + sw);
    }

    float oacc[8][4];
#pragma unroll
    for (int i = 0; i < 8; i++)
#pragma unroll
        for (int j = 0; j < 4; j++) oacc[i][j] = 0.0f;
    float m0 = -3.0e38f, m1 = -3.0e38f, l0 = 0.0f, l1 = 0.0f;

    const int gr0 = qt * 128 + wid * 16 + (lane >> 2);
    const int cq  = (lane & 3) * 2;

    for (int kt = 0; kt <= ktlast; ++kt) {
        cp_wait<1>();       // KV chunk kt complete
        __syncthreads();
        cpKV(kt + 2, (kt + 2) % 3);
        uint32_t base = sb + 16384 + (kt % 3) * 16384;

        if (kt * 64 > qt * 128 + wid * 16 + 15) continue;

        float sacc[8][4];
#pragma unroll
        for (int i = 0; i < 8; i++)
#pragma unroll
            for (int j = 0; j < 4; j++) sacc[i][j] = 0.0f;
#pragma unroll
        for (int ks = 0; ks < 4; ks++) {
            uint32_t kh[8][2];
#pragma unroll
            for (int kp = 0; kp < 4; kp++) {
                int row = kp * 16 + (lane & 15);
                uint32_t sw = sw128((uint32_t)(row * 128 + ks * 32 + (lane & 16)));
                uint32_t t[4];
                ldmx4(t, base + sw);
                kh[kp * 2][0] = t[0]; kh[kp * 2][1] = t[2];
                kh[kp * 2 + 1][0] = t[1]; kh[kp * 2 + 1][1] = t[3];
            }
#pragma unroll
            for (int nt = 0; nt < 8; nt++)
                mma_f16(sacc[nt], qh[ks], kh[nt]);
        }

        if (kt * 64 + 63 > qt * 128 + wid * 16) {
#pragma unroll
            for (int nt = 0; nt < 8; nt++) {
                int c0 = kt * 64 + nt * 8 + cq;
                if (c0 > gr0)     sacc[nt][0] = -1e30f;
                if (c0 + 1 > gr0) sacc[nt][1] = -1e30f;
                if (c0 > gr0 + 8)     sacc[nt][2] = -1e30f;
                if (c0 + 1 > gr0 + 8) sacc[nt][3] = -1e30f;
            }
        }

        float t0 = -3.0e38f, t1 = -3.0e38f;
#pragma unroll
        for (int nt = 0; nt < 8; nt++) {
            t0 = fmaxf(t0, fmaxf(sacc[nt][0], sacc[nt][1]));
            t1 = fmaxf(t1, fmaxf(sacc[nt][2], sacc[nt][3]));
        }
        t0 = fmaxf(t0, __shfl_xor_sync(0xffffffffu, t0, 1));
        t0 = fmaxf(t0, __shfl_xor_sync(0xffffffffu, t0, 2));
        t1 = fmaxf(t1, __shfl_xor_sync(0xffffffffu, t1, 1));
        t1 = fmaxf(t1, __shfl_xor_sync(0xffffffffu, t1, 2));
        float mn0 = fmaxf(m0, t0), mn1 = fmaxf(m1, t1);
        float al0 = __expf(m0 - mn0), al1 = __expf(m1 - mn1);
        m0 = mn0; m1 = mn1;

        uint32_t pH[8][2];
        float ps0 = 0.0f, ps1 = 0.0f;
#pragma unroll
        for (int nt = 0; nt < 8; nt++) {
            float p0 = __expf(sacc[nt][0] - mn0);
            float p1 = __expf(sacc[nt][1] - mn0);
            float p2 = __expf(sacc[nt][2] - mn1);
            float p3 = __expf(sacc[nt][3] - mn1);
            ps0 += p0 + p1; ps1 += p2 + p3;
            HF2 H;
            H.h[0] = __float2half_rn(p0);
            H.h[1] = __float2half_rn(p1);
            pH[nt][0] = H.u;
            H.h[0] = __float2half_rn(p2);
            H.h[1] = __float2half_rn(p3);
            pH[nt][1] = H.u;
        }
        ps0 += __shfl_xor_sync(0xffffffffu, ps0, 1);
        ps0 += __shfl_xor_sync(0xffffffffu, ps0, 2);
        ps1 += __shfl_xor_sync(0xffffffffu, ps1, 1);
        ps1 += __shfl_xor_sync(0xffffffffu, ps1, 2);
        l0 = l0 * al0 + ps0;
        l1 = l1 * al1 + ps1;

#pragma unroll
        for (int dt = 0; dt < 8; dt++) {
            oacc[dt][0] *= al0; oacc[dt][1] *= al0;
            oacc[dt][2] *= al1; oacc[dt][3] *= al1;
        }

#pragma unroll
        for (int ks = 0; ks < 4; ks++) {
            uint32_t aH[4] = { pH[2 * ks][0], pH[2 * ks][1], pH[2 * ks + 1][0], pH[2 * ks + 1][1] };
#pragma unroll
            for (int dp = 0; dp < 4; dp++) {
                uint32_t sw = sw128((uint32_t)((ks * 16 + (lane & 15)) * 128 + dp * 32 + (lane & 16)));
                uint32_t th[4];
                ldmx4t(th, base + 8192 + sw);
                uint32_t b0h[2] = { th[0], th[1] }, b1h[2] = { th[2], th[3] };
                mma_f16(oacc[2 * dp],     aH, b0h);
                mma_f16(oacc[2 * dp + 1], aH, b1h);
            }
        }
    }

    float inv0 = 1.0f / l0, inv1 = 1.0f / l1;
#pragma unroll
    for (int dt = 0; dt < 8; dt++) {
        int cg = dt * 8 + cq;
        size_t off0 = (seq0 + gr0) * EMB + hoff + cg;
        size_t off1 = (seq0 + gr0 + 8) * EMB + hoff + cg;
        HF2 H;
        H.h[0] = __float2half_rn(oacc[dt][0] * inv0);
        H.h[1] = __float2half_rn(oacc[dt][1] * inv0);
        *(uint32_t*)(Oh + off0) = H.u;
        H.h[0] = __float2half_rn(oacc[dt][2] * inv1);
        H.h[1] = __float2half_rn(oacc[dt][3] * inv1);
        *(uint32_t*)(Oh + off1) = H.u;
    }
}

// ---------------- orchestration ----------------------------------------------
extern "C" void kernel_launch(void* const* d_in, const int* in_sizes, int n_in,
                              void* d_out, int out_size) {
    (void)in_sizes; (void)n_in; (void)out_size;
    const float* x    = (const float*)d_in[0];
    const float* Wq_w = (const float*)d_in[1];
    const float* Wq_b = (const float*)d_in[2];
    const float* Wk_w = (const float*)d_in[3];
    const float* Wk_b = (const float*)d_in[4];
    const float* Wv_w = (const float*)d_in[5];
    const float* Wv_b = (const float*)d_in[6];
    const float* Wo_w = (const float*)d_in[7];
    const float* Wo_b = (const float*)d_in[8];
    const float* l1_w = (const float*)d_in[9];
    const float* l1_b = (const float*)d_in[10];
    const float* l2_w = (const float*)d_in[11];
    const float* l2_b = (const float*)d_in[12];
    const float* n1s  = (const float*)d_in[13];
    const float* n1b  = (const float*)d_in[14];
    const float* n2s  = (const float*)d_in[15];
    const float* n2b  = (const float*)d_in[16];
    float* out = (float*)d_out;

    float *x1, *rs, *rq, *var;
    cudaGetSymbolAddress((void**)&x1,  g_x1);
    cudaGetSymbolAddress((void**)&rs,  g_rowsum);
    cudaGetSymbolAddress((void**)&rq,  g_rowsq);
    cudaGetSymbolAddress((void**)&var, g_var);

    __half *h, *ctx, *ff, *qh, *kh, *vh;
    __half *wq, *wk, *wv, *wo, *l1, *l2;
    cudaGetSymbolAddress((void**)&h,  g_h);
    cudaGetSymbolAddress((void**)&qh, g_qh);
    cudaGetSymbolAddress((void**)&kh, g_kh);
    cudaGetSymbolAddress((void**)&vh, g_vh);
    cudaGetSymbolAddress((void**)&ctx, g_ctx);
    cudaGetSymbolAddress((void**)&ff, g_ff);
    cudaGetSymbolAddress((void**)&wq, g_wq);
    cudaGetSymbolAddress((void**)&wk, g_wk);
    cudaGetSymbolAddress((void**)&wv, g_wv);
    cudaGetSymbolAddress((void**)&wo, g_wo);
    cudaGetSymbolAddress((void**)&l1, g_l1);
    cudaGetSymbolAddress((void**)&l2, g_l2);

    cudaFuncSetAttribute((const void*)attn_tc_kernel,
                         cudaFuncAttributeMaxDynamicSharedMemorySize, ATT_SMEM);
    cudaFuncSetAttribute((const void*)qkv_kernel,
                         cudaFuncAttributeMaxDynamicSharedMemorySize, MM_SMEM);
    cudaFuncSetAttribute((const void*)mmagemm_kernel<MODE_BIAS_RES>,
                         cudaFuncAttributeMaxDynamicSharedMemorySize, MM_SMEM);
    cudaFuncSetAttribute((const void*)mmagemm_kernel<MODE_GELU_HI>,
                         cudaFuncAttributeMaxDynamicSharedMemorySize, MM_SMEM);

    const int LN_BLOCKS = (N_TOK * EMB / 4) / 256;
    dim3 blk(256);
    dim3 gP(EMB / 128, N_TOK / 128);
    dim3 gF(DFF / 128, N_TOK / 128);
    dim3 gQKV(3 * EMB / 128, N_TOK / 128);

    // fused weight split (hi only)
    split_all_kernel<<<SPLIT_TOTAL4 / 256, 256>>>(Wq_w, Wk_w, Wv_w, Wo_w, l1_w, l2_w,
                                                  wq, wk, wv, wo, l1, l2);

    // LN1 -> h (hi only)
    rowstats_kernel<<<N_TOK, 256>>>(x, rs, rq);
    finalize_var_kernel<<<1, 256>>>(rs, rq, var);
    ln_apply_hi_kernel<<<LN_BLOCKS, 256>>>(x, rs, var, n1s, n1b, h);

    // fused QKV projections (1-pass; Q pre-scaled 1/8)
    qkv_kernel<<<gQKV, blk, MM_SMEM>>>(h, wq, wk, wv, Wq_b, Wk_b, Wv_b, qh, kh, vh);

    // attention -> ctx
    attn_tc_kernel<<<dim3(TSEQ / 128, 64), 256, ATT_SMEM>>>(qh, kh, vh, ctx);

    // output projection + residual
    mmagemm_kernel<MODE_BIAS_RES><<<gP, blk, MM_SMEM>>>(
        ctx, wo, Wo_b, x, x1, nullptr, EMB, EMB, 1.0f);

    // LN2 -> h (hi only)
    rowstats_kernel<<<N_TOK, 256>>>(x1, rs, rq);
    finalize_var_kernel<<<1, 256>>>(rs, rq, var);
    ln_apply_hi_kernel<<<LN_BLOCKS, 256>>>(x1, rs, var, n2s, n2b, h);

    // FFN
    mmagemm_kernel<MODE_GELU_HI><<<gF, blk, MM_SMEM>>>(
        h, l1, l1_b, nullptr, nullptr, ff, DFF, EMB, 1.0f);
    mmagemm_kernel<MODE_BIAS_RES><<<gP, blk, MM_SMEM>>>(
        ff, l2, l2_b, x1, out, nullptr, EMB, DFF, 1.0f);
}